// round 2
// baseline (speedup 1.0000x reference)
#include <cuda_runtime.h>
#include <cuda_bf16.h>

#define B 512
#define S 1024
#define I 20
#define H 64
#define G 256  // 4*H gates

// ---- scratch (device globals; no allocation allowed) ----
__device__ int   g_tok[B * S];     // token index per (b,s), -1 if padding
__device__ int   g_len[B];         // true sequence length
__device__ float g_h[2][B * H];    // final hidden states fw/bw
__device__ float g_avblock[B * 80];

__device__ __forceinline__ float fsig(float x) {
    return 1.0f / (1.0f + __expf(-x));
}
__device__ __forceinline__ float ftanh(float x) {
    float t = __expf(2.0f * x);
    return (t - 1.0f) * (1.0f / (t + 1.0f));
}

// ============================================================
// Kernel 1: tokenize one-hot input + compute lengths
// grid: B blocks x 256 threads
// ============================================================
__global__ void k_tokenize(const float* __restrict__ input1) {
    int b = blockIdx.x;
    int tid = threadIdx.x;
    __shared__ int s_cnt[256];
    int cnt = 0;
    for (int s = tid; s < S; s += 256) {
        const float4* row = (const float4*)(input1 + ((size_t)b * S + s) * I);
        int t = -1;
        #pragma unroll
        for (int q = 0; q < 5; q++) {
            float4 v = row[q];
            if (v.x > 0.5f) t = q * 4 + 0;
            if (v.y > 0.5f) t = q * 4 + 1;
            if (v.z > 0.5f) t = q * 4 + 2;
            if (v.w > 0.5f) t = q * 4 + 3;
        }
        g_tok[b * S + s] = t;
        if (t >= 0) cnt++;
    }
    s_cnt[tid] = cnt;
    __syncthreads();
    for (int off = 128; off > 0; off >>= 1) {
        if (tid < off) s_cnt[tid] += s_cnt[tid + off];
        __syncthreads();
    }
    if (tid == 0) g_len[b] = s_cnt[0];
}

// ============================================================
// Kernel 2: LSTM, one block per (batch, direction)
// 256 threads; thread g owns gate row g (W_hh row in registers)
// ============================================================
__global__ void __launch_bounds__(256, 2)
k_lstm(const float* __restrict__ W_ih_f, const float* __restrict__ W_hh_f,
       const float* __restrict__ b_f,
       const float* __restrict__ W_ih_b, const float* __restrict__ W_hh_b,
       const float* __restrict__ b_b) {
    int b   = blockIdx.x;
    int dir = blockIdx.y;
    int g   = threadIdx.x;

    const float* W_ih = dir ? W_ih_b : W_ih_f;
    const float* W_hh = dir ? W_hh_b : W_hh_f;
    const float* bias = dir ? b_b    : b_f;

    __shared__ float s_Wih[I * G];   // transposed: [i][g]
    __shared__ float s_h[H];
    __shared__ float s_gate[G];
    __shared__ int   s_tok[S];

    // stage W_ih transposed (conflict-free gather later)
    for (int idx = g; idx < G * I; idx += 256) {
        int gg = idx / I, ii = idx % I;
        s_Wih[ii * G + gg] = W_ih[idx];
    }
    // stage tokens
    for (int s = g; s < S; s += 256) s_tok[s] = g_tok[b * S + s];
    // W_hh row -> registers
    float wreg[H];
    {
        const float4* w4 = (const float4*)(W_hh + g * H);
        #pragma unroll
        for (int q = 0; q < H / 4; q++) {
            float4 v = w4[q];
            wreg[q * 4 + 0] = v.x; wreg[q * 4 + 1] = v.y;
            wreg[q * 4 + 2] = v.z; wreg[q * 4 + 3] = v.w;
        }
    }
    float breg = bias[g];
    float c = 0.0f;
    if (g < H) s_h[g] = 0.0f;
    __syncthreads();

    for (int t = 0; t < S; t++) {
        int s   = dir ? (S - 1 - t) : t;
        int tok = s_tok[s];
        float gv = breg;
        if (tok >= 0) gv += s_Wih[tok * G + g];
        #pragma unroll
        for (int j0 = 0; j0 < H; j0 += 4) {
            float4 h4 = *(const float4*)(s_h + j0);
            gv = fmaf(wreg[j0 + 0], h4.x, gv);
            gv = fmaf(wreg[j0 + 1], h4.y, gv);
            gv = fmaf(wreg[j0 + 2], h4.z, gv);
            gv = fmaf(wreg[j0 + 3], h4.w, gv);
        }
        s_gate[g] = gv;
        __syncthreads();
        if (g < H) {
            float ig = s_gate[g];
            float fg = s_gate[H + g];
            float gg = s_gate[2 * H + g];
            float og = s_gate[3 * H + g];
            c = fsig(fg) * c + fsig(ig) * ftanh(gg);
            s_h[g] = fsig(og) * ftanh(c);
        }
        __syncthreads();
    }

    if (g < H) g_h[dir][b * H + g] = s_h[g];
}

// ============================================================
// Kernel 3: conv1 (token gather) + torch-reshape + ragged 4-bin mean
// grid: B blocks x 128 threads
// ============================================================
__global__ void k_avblock(const float* __restrict__ conv1_w) {
    int b = blockIdx.x;
    int tid = threadIdx.x;
    __shared__ int   s_tok[S];
    __shared__ float s_w[I * I];
    for (int s = tid; s < S; s += 128) s_tok[s] = g_tok[b * S + s];
    for (int i = tid; i < I * I; i += 128) s_w[i] = conv1_w[i];
    __syncthreads();

    int bw = g_len[b] / 4;
    if (tid < 80) {
        int k = tid / I, cc = tid % I;
        float sum = 0.0f;
        for (int s = k * bw; s < (k + 1) * bw; s++) {
            // c1 computed as [20,S] per batch, torch-reshaped to [S,20]:
            int flat = s * I + cc;
            int ch = flat >> 10;       // flat / S  (S=1024)
            int p  = flat & (S - 1);   // flat % S
            int tk = s_tok[p];
            if (tk >= 0) sum += s_w[ch * I + tk];
        }
        g_avblock[b * 80 + tid] = sum / (float)bw;
    }
}

// ============================================================
// Kernel 4: conv2+relu, concat, fc1, fc2, softmax
// grid: B blocks x 128 threads
// ============================================================
__global__ void k_head(const float* __restrict__ conv2_w,
                       const float* __restrict__ conv2_b,
                       const float* __restrict__ fc1_w,
                       const float* __restrict__ fc1_b,
                       const float* __restrict__ fc2_w,
                       const float* __restrict__ fc2_b,
                       float* __restrict__ out) {
    int b = blockIdx.x;
    int tid = threadIdx.x;
    __shared__ float s_m[228];
    __shared__ float s_av[80];
    __shared__ float s_f[64];

    if (tid < 64)            s_m[tid]      = g_h[0][b * H + tid];
    else if (tid < 128)      s_m[tid]      = g_h[1][b * H + tid - 64];
    if (tid < 80)            s_av[tid]     = g_avblock[b * 80 + tid];
    __syncthreads();

    if (tid < 100) {
        float acc = conv2_b[tid];
        const float* w = conv2_w + tid * 80;
        #pragma unroll 8
        for (int j = 0; j < 80; j++) acc = fmaf(s_av[j], w[j], acc);
        s_m[128 + tid] = fmaxf(acc, 0.0f);
    }
    __syncthreads();

    if (tid < 64) {
        float acc = fc1_b[tid];
        const float* w = fc1_w + tid * 228;
        for (int j = 0; j < 228; j++) acc = fmaf(s_m[j], w[j], acc);
        s_f[tid] = acc;
    }
    __syncthreads();

    if (tid == 0) {
        float a0 = fc2_b[0], a1 = fc2_b[1];
        #pragma unroll 8
        for (int j = 0; j < 64; j++) {
            a0 = fmaf(s_f[j], fc2_w[j], a0);
            a1 = fmaf(s_f[j], fc2_w[64 + j], a1);
        }
        float m  = fmaxf(a0, a1);
        float e0 = __expf(a0 - m), e1 = __expf(a1 - m);
        float inv = 1.0f / (e0 + e1);
        out[b * 2 + 0] = e0 * inv;
        out[b * 2 + 1] = e1 * inv;
    }
}

extern "C" void kernel_launch(void* const* d_in, const int* in_sizes, int n_in,
                              void* d_out, int out_size) {
    const float* input1  = (const float*)d_in[0];
    const float* W_ih_f  = (const float*)d_in[1];
    const float* W_hh_f  = (const float*)d_in[2];
    const float* b_f     = (const float*)d_in[3];
    const float* W_ih_b  = (const float*)d_in[4];
    const float* W_hh_b  = (const float*)d_in[5];
    const float* b_b     = (const float*)d_in[6];
    const float* conv1_w = (const float*)d_in[7];
    const float* conv2_w = (const float*)d_in[8];
    const float* conv2_b = (const float*)d_in[9];
    const float* fc1_w   = (const float*)d_in[10];
    const float* fc1_b   = (const float*)d_in[11];
    const float* fc2_w   = (const float*)d_in[12];
    const float* fc2_b   = (const float*)d_in[13];
    float* out = (float*)d_out;

    k_tokenize<<<B, 256>>>(input1);
    dim3 lgrid(B, 2);
    k_lstm<<<lgrid, 256>>>(W_ih_f, W_hh_f, b_f, W_ih_b, W_hh_b, b_b);
    k_avblock<<<B, 128>>>(conv1_w);
    k_head<<<B, 128>>>(conv2_w, conv2_b, fc1_w, fc1_b, fc2_w, fc2_b, out);
}

// round 3
// speedup vs baseline: 1.2701x; 1.2701x over previous
#include <cuda_runtime.h>
#include <cuda_bf16.h>

#define B 512
#define S 1024
#define I 20
#define H 64
#define G 256  // 4*H gates

// ---- scratch (device globals; no allocation allowed) ----
__device__ int   g_tok[B * S];     // token index per (b,s), -1 if padding
__device__ int   g_len[B];         // true sequence length
__device__ float g_h[2][B * H];    // final hidden states fw/bw
__device__ float g_avblock[B * 80];

__device__ __forceinline__ float fsig(float x) {
    return 1.0f / (1.0f + __expf(-x));
}
__device__ __forceinline__ float ftanh(float x) {
    float t = __expf(2.0f * x);
    return (t - 1.0f) * (1.0f / (t + 1.0f));
}

// ---- packed f32x2 helpers (SASS FFMA2 path, PTX-only) ----
__device__ __forceinline__ unsigned long long pack2(float lo, float hi) {
    unsigned long long r;
    asm("mov.b64 %0, {%1, %2};" : "=l"(r) : "f"(lo), "f"(hi));
    return r;
}
__device__ __forceinline__ void unpack2(unsigned long long v, float& lo, float& hi) {
    asm("mov.b64 {%0, %1}, %2;" : "=f"(lo), "=f"(hi) : "l"(v));
}
__device__ __forceinline__ unsigned long long fma2(unsigned long long a,
                                                   unsigned long long b,
                                                   unsigned long long c) {
    unsigned long long d;
    asm("fma.rn.f32x2 %0, %1, %2, %3;" : "=l"(d) : "l"(a), "l"(b), "l"(c));
    return d;
}
__device__ __forceinline__ unsigned long long add2(unsigned long long a,
                                                   unsigned long long b) {
    unsigned long long d;
    asm("add.rn.f32x2 %0, %1, %2;" : "=l"(d) : "l"(a), "l"(b));
    return d;
}

// ============================================================
// Kernel 1: tokenize one-hot input + compute lengths
// ============================================================
__global__ void k_tokenize(const float* __restrict__ input1) {
    int b = blockIdx.x;
    int tid = threadIdx.x;
    __shared__ int s_cnt[256];
    int cnt = 0;
    for (int s = tid; s < S; s += 256) {
        const float4* row = (const float4*)(input1 + ((size_t)b * S + s) * I);
        int t = -1;
        #pragma unroll
        for (int q = 0; q < 5; q++) {
            float4 v = row[q];
            if (v.x > 0.5f) t = q * 4 + 0;
            if (v.y > 0.5f) t = q * 4 + 1;
            if (v.z > 0.5f) t = q * 4 + 2;
            if (v.w > 0.5f) t = q * 4 + 3;
        }
        g_tok[b * S + s] = t;
        if (t >= 0) cnt++;
    }
    s_cnt[tid] = cnt;
    __syncthreads();
    for (int off = 128; off > 0; off >>= 1) {
        if (tid < off) s_cnt[tid] += s_cnt[tid + off];
        __syncthreads();
    }
    if (tid == 0) g_len[b] = s_cnt[0];
}

// ============================================================
// Kernel 2: LSTM with packed f32x2 FMAs.
// 128 threads per (batch, direction); thread t owns gate rows 2t, 2t+1.
// W_hh pairs live in 64 b64 registers; h is duplicated in SMEM.
// ============================================================
__global__ void __launch_bounds__(128, 3)
k_lstm(const float* __restrict__ W_ih_f, const float* __restrict__ W_hh_f,
       const float* __restrict__ b_f,
       const float* __restrict__ W_ih_b, const float* __restrict__ W_hh_b,
       const float* __restrict__ b_b) {
    int b   = blockIdx.x;
    int dir = blockIdx.y;
    int t   = threadIdx.x;  // 0..127

    const float* W_ih = dir ? W_ih_b : W_ih_f;
    const float* W_hh = dir ? W_hh_b : W_hh_f;
    const float* bias = dir ? b_b    : b_f;

    __shared__ float s_Wihb[21 * G];          // [tok][gate], bias fused; row 20 = bias only
    __shared__ __align__(16) float s_h2[2 * H];  // duplicated pairs (h_j, h_j)
    __shared__ __align__(8)  float s_gate[G];
    __shared__ int s_tok[S];

    // stage W_ih transposed with bias fused (+ zero row for padding steps)
    for (int idx = t; idx < 21 * G; idx += 128) {
        int i  = idx >> 8;        // token row
        int gg = idx & 255;       // gate
        float v = bias[gg];
        if (i < I) v += W_ih[gg * I + i];
        s_Wihb[idx] = v;
    }
    // stage tokens
    for (int s = t; s < S; s += 128) s_tok[s] = g_tok[b * S + s];

    // W_hh rows 2t, 2t+1 -> packed registers
    unsigned long long w2[H];
    {
        const float4* r0 = (const float4*)(W_hh + (2 * t) * H);
        const float4* r1 = (const float4*)(W_hh + (2 * t + 1) * H);
        #pragma unroll
        for (int q = 0; q < H / 4; q++) {
            float4 a = r0[q];
            float4 c = r1[q];
            w2[q * 4 + 0] = pack2(a.x, c.x);
            w2[q * 4 + 1] = pack2(a.y, c.y);
            w2[q * 4 + 2] = pack2(a.z, c.z);
            w2[q * 4 + 3] = pack2(a.w, c.w);
        }
    }

    float c_state = 0.0f;
    if (t < H) { s_h2[2 * t] = 0.0f; s_h2[2 * t + 1] = 0.0f; }
    __syncthreads();

    for (int step = 0; step < S; step++) {
        int s   = dir ? (S - 1 - step) : step;
        int tok = s_tok[s];
        int row = (tok >= 0) ? tok : 20;

        // init accumulators: acc0 carries bias + one-hot W_ih contribution
        float2 init = *(const float2*)(s_Wihb + row * G + 2 * t);
        unsigned long long acc0 = pack2(init.x, init.y);
        unsigned long long acc1 = pack2(0.0f, 0.0f);

        #pragma unroll
        for (int j = 0; j < H; j += 2) {
            ulonglong2 hh = *(const ulonglong2*)(s_h2 + 2 * j);  // (h_j,h_j),(h_j+1,h_j+1)
            acc0 = fma2(w2[j],     hh.x, acc0);
            acc1 = fma2(w2[j + 1], hh.y, acc1);
        }
        unsigned long long acc = add2(acc0, acc1);

        float glo, ghi;
        unpack2(acc, glo, ghi);
        *(float2*)(s_gate + 2 * t) = make_float2(glo, ghi);
        __syncthreads();

        if (t < H) {
            float ig = s_gate[t];
            float fg = s_gate[H + t];
            float gg = s_gate[2 * H + t];
            float og = s_gate[3 * H + t];
            c_state = fsig(fg) * c_state + fsig(ig) * ftanh(gg);
            float h = fsig(og) * ftanh(c_state);
            *(float2*)(s_h2 + 2 * t) = make_float2(h, h);
        }
        __syncthreads();
    }

    if (t < H) g_h[dir][b * H + t] = s_h2[2 * t];
}

// ============================================================
// Kernel 3: conv1 (token gather) + torch-reshape + ragged 4-bin mean
// ============================================================
__global__ void k_avblock(const float* __restrict__ conv1_w) {
    int b = blockIdx.x;
    int tid = threadIdx.x;
    __shared__ int   s_tok[S];
    __shared__ float s_w[I * I];
    for (int s = tid; s < S; s += 128) s_tok[s] = g_tok[b * S + s];
    for (int i = tid; i < I * I; i += 128) s_w[i] = conv1_w[i];
    __syncthreads();

    int bw = g_len[b] / 4;
    if (tid < 80) {
        int k = tid / I, cc = tid % I;
        float sum = 0.0f;
        for (int s = k * bw; s < (k + 1) * bw; s++) {
            int flat = s * I + cc;
            int ch = flat >> 10;       // flat / S  (S=1024)
            int p  = flat & (S - 1);   // flat % S
            int tk = s_tok[p];
            if (tk >= 0) sum += s_w[ch * I + tk];
        }
        g_avblock[b * 80 + tid] = sum / (float)bw;
    }
}

// ============================================================
// Kernel 4: conv2+relu, concat, fc1, fc2, softmax
// ============================================================
__global__ void k_head(const float* __restrict__ conv2_w,
                       const float* __restrict__ conv2_b,
                       const float* __restrict__ fc1_w,
                       const float* __restrict__ fc1_b,
                       const float* __restrict__ fc2_w,
                       const float* __restrict__ fc2_b,
                       float* __restrict__ out) {
    int b = blockIdx.x;
    int tid = threadIdx.x;
    __shared__ float s_m[228];
    __shared__ float s_av[80];
    __shared__ float s_f[64];

    if (tid < 64)            s_m[tid] = g_h[0][b * H + tid];
    else if (tid < 128)      s_m[tid] = g_h[1][b * H + tid - 64];
    if (tid < 80)            s_av[tid] = g_avblock[b * 80 + tid];
    __syncthreads();

    if (tid < 100) {
        float acc = conv2_b[tid];
        const float* w = conv2_w + tid * 80;
        #pragma unroll 8
        for (int j = 0; j < 80; j++) acc = fmaf(s_av[j], w[j], acc);
        s_m[128 + tid] = fmaxf(acc, 0.0f);
    }
    __syncthreads();

    if (tid < 64) {
        float acc = fc1_b[tid];
        const float* w = fc1_w + tid * 228;
        for (int j = 0; j < 228; j++) acc = fmaf(s_m[j], w[j], acc);
        s_f[tid] = acc;
    }
    __syncthreads();

    if (tid == 0) {
        float a0 = fc2_b[0], a1 = fc2_b[1];
        #pragma unroll 8
        for (int j = 0; j < 64; j++) {
            a0 = fmaf(s_f[j], fc2_w[j], a0);
            a1 = fmaf(s_f[j], fc2_w[64 + j], a1);
        }
        float m  = fmaxf(a0, a1);
        float e0 = __expf(a0 - m), e1 = __expf(a1 - m);
        float inv = 1.0f / (e0 + e1);
        out[b * 2 + 0] = e0 * inv;
        out[b * 2 + 1] = e1 * inv;
    }
}

extern "C" void kernel_launch(void* const* d_in, const int* in_sizes, int n_in,
                              void* d_out, int out_size) {
    const float* input1  = (const float*)d_in[0];
    const float* W_ih_f  = (const float*)d_in[1];
    const float* W_hh_f  = (const float*)d_in[2];
    const float* b_f     = (const float*)d_in[3];
    const float* W_ih_b  = (const float*)d_in[4];
    const float* W_hh_b  = (const float*)d_in[5];
    const float* b_b     = (const float*)d_in[6];
    const float* conv1_w = (const float*)d_in[7];
    const float* conv2_w = (const float*)d_in[8];
    const float* conv2_b = (const float*)d_in[9];
    const float* fc1_w   = (const float*)d_in[10];
    const float* fc1_b   = (const float*)d_in[11];
    const float* fc2_w   = (const float*)d_in[12];
    const float* fc2_b   = (const float*)d_in[13];
    float* out = (float*)d_out;

    k_tokenize<<<B, 256>>>(input1);
    dim3 lgrid(B, 2);
    k_lstm<<<lgrid, 128>>>(W_ih_f, W_hh_f, b_f, W_ih_b, W_hh_b, b_b);
    k_avblock<<<B, 128>>>(conv1_w);
    k_head<<<B, 128>>>(conv2_w, conv2_b, fc1_w, fc1_b, fc2_w, fc2_b, out);
}

// round 4
// speedup vs baseline: 1.6297x; 1.2832x over previous
#include <cuda_runtime.h>
#include <cuda_bf16.h>

#define B 512
#define S 1024
#define I 20
#define H 64
#define G 256  // 4*H gates

// ---- scratch (device globals; no allocation allowed) ----
__device__ int   g_tok[B * S];     // token index per (b,s), -1 if padding
__device__ int   g_len[B];         // true sequence length
__device__ float g_h[2][B * H];    // final hidden states fw/bw
__device__ float g_avblock[B * 80];

__device__ __forceinline__ float tanh_fast(float x) {
    float y;
    asm("tanh.approx.f32 %0, %1;" : "=f"(y) : "f"(x));
    return y;
}
__device__ __forceinline__ float sig_fast(float x) {
    return fmaf(tanh_fast(0.5f * x), 0.5f, 0.5f);
}

// ---- packed f32x2 helpers (SASS FFMA2 path, PTX-only) ----
__device__ __forceinline__ unsigned long long pack2(float lo, float hi) {
    unsigned long long r;
    asm("mov.b64 %0, {%1, %2};" : "=l"(r) : "f"(lo), "f"(hi));
    return r;
}
__device__ __forceinline__ void unpack2(unsigned long long v, float& lo, float& hi) {
    asm("mov.b64 {%0, %1}, %2;" : "=f"(lo), "=f"(hi) : "l"(v));
}
__device__ __forceinline__ unsigned long long fma2(unsigned long long a,
                                                   unsigned long long b,
                                                   unsigned long long c) {
    unsigned long long d;
    asm("fma.rn.f32x2 %0, %1, %2, %3;" : "=l"(d) : "l"(a), "l"(b), "l"(c));
    return d;
}
__device__ __forceinline__ unsigned long long add2(unsigned long long a,
                                                   unsigned long long b) {
    unsigned long long d;
    asm("add.rn.f32x2 %0, %1, %2;" : "=l"(d) : "l"(a), "l"(b));
    return d;
}

// ============================================================
// Kernel 1: tokenize one-hot input + compute lengths
// ============================================================
__global__ void k_tokenize(const float* __restrict__ input1) {
    int b = blockIdx.x;
    int tid = threadIdx.x;
    __shared__ int s_cnt[256];
    int cnt = 0;
    for (int s = tid; s < S; s += 256) {
        const float4* row = (const float4*)(input1 + ((size_t)b * S + s) * I);
        int t = -1;
        #pragma unroll
        for (int q = 0; q < 5; q++) {
            float4 v = row[q];
            if (v.x > 0.5f) t = q * 4 + 0;
            if (v.y > 0.5f) t = q * 4 + 1;
            if (v.z > 0.5f) t = q * 4 + 2;
            if (v.w > 0.5f) t = q * 4 + 3;
        }
        g_tok[b * S + s] = t;
        if (t >= 0) cnt++;
    }
    s_cnt[tid] = cnt;
    __syncthreads();
    for (int off = 128; off > 0; off >>= 1) {
        if (tid < off) s_cnt[tid] += s_cnt[tid + off];
        __syncthreads();
    }
    if (tid == 0) g_len[b] = s_cnt[0];
}

// ============================================================
// Kernel 2: LSTM. 256 threads per (batch, direction).
// Thread t: gate pair p = t & 127 (gates 2p, 2p+1), K-half kh = t >> 7.
// 32 packed (b64) weight regs per thread -> ~80 regs -> occ 3 (24 warps/SM).
// ============================================================
__global__ void __launch_bounds__(256, 3)
k_lstm(const float* __restrict__ W_ih_f, const float* __restrict__ W_hh_f,
       const float* __restrict__ b_f,
       const float* __restrict__ W_ih_b, const float* __restrict__ W_hh_b,
       const float* __restrict__ b_b) {
    int b   = blockIdx.x;
    int dir = blockIdx.y;
    int t   = threadIdx.x;        // 0..255
    int p   = t & 127;            // gate pair index
    int kh  = t >> 7;             // K half (0 or 1)
    int kbase = kh * 32;

    const float* W_ih = dir ? W_ih_b : W_ih_f;
    const float* W_hh = dir ? W_hh_b : W_hh_f;
    const float* bias = dir ? b_b    : b_f;

    __shared__ float s_Wihb[21 * G];             // [tok][gate], bias fused; row 20 = bias only
    __shared__ __align__(16) float s_h2[2 * H];  // duplicated pairs (h_j, h_j)
    __shared__ __align__(8)  float s_part[2 * G];// [kh][gate] partial sums
    __shared__ int s_tok[S];

    // stage W_ih transposed with bias fused (+ bias-only row for padding steps)
    for (int idx = t; idx < 21 * G; idx += 256) {
        int i  = idx >> 8;
        int gg = idx & 255;
        float v = bias[gg];
        if (i < I) v += W_ih[gg * I + i];
        s_Wihb[idx] = v;
    }
    for (int s = t; s < S; s += 256) s_tok[s] = g_tok[b * S + s];

    // weights: rows 2p, 2p+1, columns [kbase, kbase+32) -> 32 packed regs
    unsigned long long w2[32];
    {
        const float4* r0 = (const float4*)(W_hh + (2 * p) * H + kbase);
        const float4* r1 = (const float4*)(W_hh + (2 * p + 1) * H + kbase);
        #pragma unroll
        for (int q = 0; q < 8; q++) {
            float4 a = r0[q];
            float4 c = r1[q];
            w2[q * 4 + 0] = pack2(a.x, c.x);
            w2[q * 4 + 1] = pack2(a.y, c.y);
            w2[q * 4 + 2] = pack2(a.z, c.z);
            w2[q * 4 + 3] = pack2(a.w, c.w);
        }
    }

    float c_state = 0.0f;
    if (t < H) { s_h2[2 * t] = 0.0f; s_h2[2 * t + 1] = 0.0f; }
    __syncthreads();

    for (int step = 0; step < S; step++) {
        int s   = dir ? (S - 1 - step) : step;
        int tok = s_tok[s];
        int row = (tok >= 0) ? tok : 20;

        unsigned long long acc0, acc1;
        if (kh == 0) {
            float2 init = *(const float2*)(s_Wihb + row * G + 2 * p);
            acc0 = pack2(init.x, init.y);
        } else {
            acc0 = 0ULL;
        }
        acc1 = 0ULL;

        #pragma unroll
        for (int j = 0; j < 32; j += 2) {
            ulonglong2 hh = *(const ulonglong2*)(s_h2 + 2 * (kbase + j));
            acc0 = fma2(w2[j],     hh.x, acc0);
            acc1 = fma2(w2[j + 1], hh.y, acc1);
        }
        unsigned long long acc = add2(acc0, acc1);

        float glo, ghi;
        unpack2(acc, glo, ghi);
        *(float2*)(s_part + kh * G + 2 * p) = make_float2(glo, ghi);
        __syncthreads();

        if (t < H) {
            float ig = s_part[t]           + s_part[G + t];
            float fg = s_part[H + t]       + s_part[G + H + t];
            float gg = s_part[2 * H + t]   + s_part[G + 2 * H + t];
            float og = s_part[3 * H + t]   + s_part[G + 3 * H + t];
            c_state = sig_fast(fg) * c_state + sig_fast(ig) * tanh_fast(gg);
            float h = sig_fast(og) * tanh_fast(c_state);
            *(float2*)(s_h2 + 2 * t) = make_float2(h, h);
        }
        __syncthreads();
    }

    if (t < H) g_h[dir][b * H + t] = s_h2[2 * t];
}

// ============================================================
// Kernel 3: conv1 (token gather) + torch-reshape + ragged 4-bin mean
// ============================================================
__global__ void k_avblock(const float* __restrict__ conv1_w) {
    int b = blockIdx.x;
    int tid = threadIdx.x;
    __shared__ int   s_tok[S];
    __shared__ float s_w[I * I];
    for (int s = tid; s < S; s += 128) s_tok[s] = g_tok[b * S + s];
    for (int i = tid; i < I * I; i += 128) s_w[i] = conv1_w[i];
    __syncthreads();

    int bw = g_len[b] / 4;
    if (tid < 80) {
        int k = tid / I, cc = tid % I;
        float sum = 0.0f;
        for (int s = k * bw; s < (k + 1) * bw; s++) {
            int flat = s * I + cc;
            int ch = flat >> 10;       // flat / S  (S=1024)
            int pp = flat & (S - 1);   // flat % S
            int tk = s_tok[pp];
            if (tk >= 0) sum += s_w[ch * I + tk];
        }
        g_avblock[b * 80 + tid] = sum / (float)bw;
    }
}

// ============================================================
// Kernel 4: conv2+relu, concat, fc1, fc2, softmax
// ============================================================
__global__ void k_head(const float* __restrict__ conv2_w,
                       const float* __restrict__ conv2_b,
                       const float* __restrict__ fc1_w,
                       const float* __restrict__ fc1_b,
                       const float* __restrict__ fc2_w,
                       const float* __restrict__ fc2_b,
                       float* __restrict__ out) {
    int b = blockIdx.x;
    int tid = threadIdx.x;
    __shared__ float s_m[228];
    __shared__ float s_av[80];
    __shared__ float s_f[64];

    if (tid < 64)            s_m[tid] = g_h[0][b * H + tid];
    else if (tid < 128)      s_m[tid] = g_h[1][b * H + tid - 64];
    if (tid < 80)            s_av[tid] = g_avblock[b * 80 + tid];
    __syncthreads();

    if (tid < 100) {
        float acc = conv2_b[tid];
        const float* w = conv2_w + tid * 80;
        #pragma unroll 8
        for (int j = 0; j < 80; j++) acc = fmaf(s_av[j], w[j], acc);
        s_m[128 + tid] = fmaxf(acc, 0.0f);
    }
    __syncthreads();

    if (tid < 64) {
        float acc = fc1_b[tid];
        const float* w = fc1_w + tid * 228;
        for (int j = 0; j < 228; j++) acc = fmaf(s_m[j], w[j], acc);
        s_f[tid] = acc;
    }
    __syncthreads();

    if (tid == 0) {
        float a0 = fc2_b[0], a1 = fc2_b[1];
        #pragma unroll 8
        for (int j = 0; j < 64; j++) {
            a0 = fmaf(s_f[j], fc2_w[j], a0);
            a1 = fmaf(s_f[j], fc2_w[64 + j], a1);
        }
        float m  = fmaxf(a0, a1);
        float e0 = __expf(a0 - m), e1 = __expf(a1 - m);
        float inv = 1.0f / (e0 + e1);
        out[b * 2 + 0] = e0 * inv;
        out[b * 2 + 1] = e1 * inv;
    }
}

extern "C" void kernel_launch(void* const* d_in, const int* in_sizes, int n_in,
                              void* d_out, int out_size) {
    const float* input1  = (const float*)d_in[0];
    const float* W_ih_f  = (const float*)d_in[1];
    const float* W_hh_f  = (const float*)d_in[2];
    const float* b_f     = (const float*)d_in[3];
    const float* W_ih_b  = (const float*)d_in[4];
    const float* W_hh_b  = (const float*)d_in[5];
    const float* b_b     = (const float*)d_in[6];
    const float* conv1_w = (const float*)d_in[7];
    const float* conv2_w = (const float*)d_in[8];
    const float* conv2_b = (const float*)d_in[9];
    const float* fc1_w   = (const float*)d_in[10];
    const float* fc1_b   = (const float*)d_in[11];
    const float* fc2_w   = (const float*)d_in[12];
    const float* fc2_b   = (const float*)d_in[13];
    float* out = (float*)d_out;

    k_tokenize<<<B, 256>>>(input1);
    dim3 lgrid(B, 2);
    k_lstm<<<lgrid, 256>>>(W_ih_f, W_hh_f, b_f, W_ih_b, W_hh_b, b_b);
    k_avblock<<<B, 128>>>(conv1_w);
    k_head<<<B, 128>>>(conv2_w, conv2_b, fc1_w, fc1_b, fc2_w, fc2_b, out);
}

// round 5
// speedup vs baseline: 2.2809x; 1.3996x over previous
#include <cuda_runtime.h>
#include <cuda_bf16.h>

#define B 512
#define S 1024
#define I 20
#define H 64
#define G 256   // 4*H gates
#define NB 4    // batches per LSTM CTA

// ---- scratch (device globals; no allocation allowed) ----
__device__ int   g_tok[B * S];     // token index per (b,s), -1 if padding
__device__ int   g_len[B];         // true sequence length
__device__ float g_h[2][B * H];    // final hidden states fw/bw
__device__ float g_avblock[B * 80];

__device__ __forceinline__ float tanh_fast(float x) {
    float y;
    asm("tanh.approx.f32 %0, %1;" : "=f"(y) : "f"(x));
    return y;
}
__device__ __forceinline__ float sig_fast(float x) {
    return fmaf(tanh_fast(0.5f * x), 0.5f, 0.5f);
}

// ---- packed f32x2 helpers (SASS FFMA2 path, PTX-only) ----
__device__ __forceinline__ unsigned long long pack2(float lo, float hi) {
    unsigned long long r;
    asm("mov.b64 %0, {%1, %2};" : "=l"(r) : "f"(lo), "f"(hi));
    return r;
}
__device__ __forceinline__ void unpack2(unsigned long long v, float& lo, float& hi) {
    asm("mov.b64 {%0, %1}, %2;" : "=f"(lo), "=f"(hi) : "l"(v));
}
__device__ __forceinline__ unsigned long long fma2(unsigned long long a,
                                                   unsigned long long b,
                                                   unsigned long long c) {
    unsigned long long d;
    asm("fma.rn.f32x2 %0, %1, %2, %3;" : "=l"(d) : "l"(a), "l"(b), "l"(c));
    return d;
}

// ============================================================
// Kernel 1: tokenize one-hot input + compute lengths
// ============================================================
__global__ void k_tokenize(const float* __restrict__ input1) {
    int b = blockIdx.x;
    int tid = threadIdx.x;
    __shared__ int s_cnt[256];
    int cnt = 0;
    for (int s = tid; s < S; s += 256) {
        const float4* row = (const float4*)(input1 + ((size_t)b * S + s) * I);
        int t = -1;
        #pragma unroll
        for (int q = 0; q < 5; q++) {
            float4 v = row[q];
            if (v.x > 0.5f) t = q * 4 + 0;
            if (v.y > 0.5f) t = q * 4 + 1;
            if (v.z > 0.5f) t = q * 4 + 2;
            if (v.w > 0.5f) t = q * 4 + 3;
        }
        g_tok[b * S + s] = t;
        if (t >= 0) cnt++;
    }
    s_cnt[tid] = cnt;
    __syncthreads();
    for (int off = 128; off > 0; off >>= 1) {
        if (tid < off) s_cnt[tid] += s_cnt[tid + off];
        __syncthreads();
    }
    if (tid == 0) g_len[b] = s_cnt[0];
}

// ============================================================
// Kernel 2: persistent-batched LSTM.
// One CTA = 4 chains of one direction, sharing weight registers.
// 256 threads: thread t -> gate pair p = t & 127 (gates 2p,2p+1),
// K-half kh = t >> 7. Weights pair-packed (h_j, h_j+1) for FFMA2;
// horizontal lo+hi add finishes each gate.
// ============================================================
__global__ void __launch_bounds__(256, 2)
k_lstm(const float* __restrict__ W_ih_f, const float* __restrict__ W_hh_f,
       const float* __restrict__ b_f,
       const float* __restrict__ W_ih_b, const float* __restrict__ W_hh_b,
       const float* __restrict__ b_b) {
    int b0  = blockIdx.x * NB;     // first batch of this CTA
    int dir = blockIdx.y;
    int t   = threadIdx.x;         // 0..255
    int p   = t & 127;             // gate pair index (gates 2p, 2p+1)
    int kh  = t >> 7;              // K half (0 or 1)
    int kbase = kh * 32;

    const float* W_ih = dir ? W_ih_b : W_ih_f;
    const float* W_hh = dir ? W_hh_b : W_hh_f;
    const float* bias = dir ? b_b    : b_f;

    __shared__ float s_Wihb[22 * G];          // rows 0..19 tok, 20 bias-only, 21 zeros
    __shared__ __align__(16) float s_h[NB * H];
    __shared__ __align__(8)  float s_part[2 * NB * G];  // [kh][nb][gate]
    __shared__ signed char s_tok[NB * S];

    // stage W_ih transposed with bias fused; row 20 = bias, row 21 = zeros
    for (int idx = t; idx < 22 * G; idx += 256) {
        int i  = idx >> 8;
        int gg = idx & 255;
        float v = (i < 21) ? bias[gg] : 0.0f;
        if (i < I) v += W_ih[gg * I + i];
        s_Wihb[idx] = v;
    }
    // stage tokens for all NB batches (as int8)
    for (int idx = t; idx < NB * S; idx += 256) {
        int nb = idx >> 10, s = idx & (S - 1);
        s_tok[idx] = (signed char)g_tok[(b0 + nb) * S + s];
    }

    // pair-packed weights: rows 2p, 2p+1, cols [kbase, kbase+32)
    unsigned long long wp0[16], wp1[16];
    {
        const float4* r0 = (const float4*)(W_hh + (2 * p) * H + kbase);
        const float4* r1 = (const float4*)(W_hh + (2 * p + 1) * H + kbase);
        #pragma unroll
        for (int q = 0; q < 8; q++) {
            float4 a = r0[q];
            float4 c = r1[q];
            wp0[2 * q]     = pack2(a.x, a.y);
            wp0[2 * q + 1] = pack2(a.z, a.w);
            wp1[2 * q]     = pack2(c.x, c.y);
            wp1[2 * q + 1] = pack2(c.z, c.w);
        }
    }

    // activation role: thread t -> batch anb, hidden unit hid
    int anb  = t >> 6;
    int hid  = t & 63;
    float c_state = 0.0f;
    if (t < NB * H) s_h[t] = 0.0f;
    __syncthreads();

    for (int step = 0; step < S; step++) {
        int s = dir ? (S - 1 - step) : step;

        // ---- gate phase: 4 batches with shared weight registers ----
        #pragma unroll
        for (int nb = 0; nb < NB; nb++) {
            int tok = s_tok[nb * S + s];
            int row = (kh == 0) ? ((tok >= 0) ? tok : 20) : 21;
            float2 init = *(const float2*)(s_Wihb + row * G + 2 * p);

            unsigned long long acc0 = pack2(init.x, 0.0f);
            unsigned long long acc1 = pack2(init.y, 0.0f);
            const ulonglong2* hp = (const ulonglong2*)(s_h + nb * H + kbase);
            #pragma unroll
            for (int q = 0; q < 8; q++) {
                ulonglong2 h2 = hp[q];
                acc0 = fma2(wp0[2 * q],     h2.x, acc0);
                acc0 = fma2(wp0[2 * q + 1], h2.y, acc0);
                acc1 = fma2(wp1[2 * q],     h2.x, acc1);
                acc1 = fma2(wp1[2 * q + 1], h2.y, acc1);
            }
            float l0, h0, l1, h1;
            unpack2(acc0, l0, h0);
            unpack2(acc1, l1, h1);
            *(float2*)(s_part + (kh * NB + nb) * G + 2 * p) =
                make_float2(l0 + h0, l1 + h1);
        }
        __syncthreads();

        // ---- activation phase: all 256 threads, one (batch, unit) each ----
        {
            const float* pa = s_part + anb * G + hid;          // kh = 0
            const float* pb = s_part + (NB + anb) * G + hid;   // kh = 1
            float ig = pa[0]     + pb[0];
            float fg = pa[H]     + pb[H];
            float gg = pa[2 * H] + pb[2 * H];
            float og = pa[3 * H] + pb[3 * H];
            c_state = sig_fast(fg) * c_state + sig_fast(ig) * tanh_fast(gg);
            s_h[anb * H + hid] = sig_fast(og) * tanh_fast(c_state);
        }
        __syncthreads();
    }

    g_h[dir][(b0 + anb) * H + hid] = s_h[anb * H + hid];
}

// ============================================================
// Kernel 3: conv1 (token gather) + torch-reshape + ragged 4-bin mean
// ============================================================
__global__ void k_avblock(const float* __restrict__ conv1_w) {
    int b = blockIdx.x;
    int tid = threadIdx.x;
    __shared__ int   s_tok[S];
    __shared__ float s_w[I * I];
    for (int s = tid; s < S; s += 128) s_tok[s] = g_tok[b * S + s];
    for (int i = tid; i < I * I; i += 128) s_w[i] = conv1_w[i];
    __syncthreads();

    int bw = g_len[b] / 4;
    if (tid < 80) {
        int k = tid / I, cc = tid % I;
        float sum = 0.0f;
        for (int s = k * bw; s < (k + 1) * bw; s++) {
            int flat = s * I + cc;
            int ch = flat >> 10;       // flat / S  (S=1024)
            int pp = flat & (S - 1);   // flat % S
            int tk = s_tok[pp];
            if (tk >= 0) sum += s_w[ch * I + tk];
        }
        g_avblock[b * 80 + tid] = sum / (float)bw;
    }
}

// ============================================================
// Kernel 4: conv2+relu, concat, fc1, fc2, softmax
// ============================================================
__global__ void k_head(const float* __restrict__ conv2_w,
                       const float* __restrict__ conv2_b,
                       const float* __restrict__ fc1_w,
                       const float* __restrict__ fc1_b,
                       const float* __restrict__ fc2_w,
                       const float* __restrict__ fc2_b,
                       float* __restrict__ out) {
    int b = blockIdx.x;
    int tid = threadIdx.x;
    __shared__ float s_m[228];
    __shared__ float s_av[80];
    __shared__ float s_f[64];

    if (tid < 64)            s_m[tid] = g_h[0][b * H + tid];
    else if (tid < 128)      s_m[tid] = g_h[1][b * H + tid - 64];
    if (tid < 80)            s_av[tid] = g_avblock[b * 80 + tid];
    __syncthreads();

    if (tid < 100) {
        float acc = conv2_b[tid];
        const float* w = conv2_w + tid * 80;
        #pragma unroll 8
        for (int j = 0; j < 80; j++) acc = fmaf(s_av[j], w[j], acc);
        s_m[128 + tid] = fmaxf(acc, 0.0f);
    }
    __syncthreads();

    if (tid < 64) {
        float acc = fc1_b[tid];
        const float* w = fc1_w + tid * 228;
        for (int j = 0; j < 228; j++) acc = fmaf(s_m[j], w[j], acc);
        s_f[tid] = acc;
    }
    __syncthreads();

    if (tid == 0) {
        float a0 = fc2_b[0], a1 = fc2_b[1];
        #pragma unroll 8
        for (int j = 0; j < 64; j++) {
            a0 = fmaf(s_f[j], fc2_w[j], a0);
            a1 = fmaf(s_f[j], fc2_w[64 + j], a1);
        }
        float m  = fmaxf(a0, a1);
        float e0 = __expf(a0 - m), e1 = __expf(a1 - m);
        float inv = 1.0f / (e0 + e1);
        out[b * 2 + 0] = e0 * inv;
        out[b * 2 + 1] = e1 * inv;
    }
}

extern "C" void kernel_launch(void* const* d_in, const int* in_sizes, int n_in,
                              void* d_out, int out_size) {
    const float* input1  = (const float*)d_in[0];
    const float* W_ih_f  = (const float*)d_in[1];
    const float* W_hh_f  = (const float*)d_in[2];
    const float* b_f     = (const float*)d_in[3];
    const float* W_ih_b  = (const float*)d_in[4];
    const float* W_hh_b  = (const float*)d_in[5];
    const float* b_b     = (const float*)d_in[6];
    const float* conv1_w = (const float*)d_in[7];
    const float* conv2_w = (const float*)d_in[8];
    const float* conv2_b = (const float*)d_in[9];
    const float* fc1_w   = (const float*)d_in[10];
    const float* fc1_b   = (const float*)d_in[11];
    const float* fc2_w   = (const float*)d_in[12];
    const float* fc2_b   = (const float*)d_in[13];
    float* out = (float*)d_out;

    k_tokenize<<<B, 256>>>(input1);
    dim3 lgrid(B / NB, 2);
    k_lstm<<<lgrid, 256>>>(W_ih_f, W_hh_f, b_f, W_ih_b, W_hh_b, b_b);
    k_avblock<<<B, 128>>>(conv1_w);
    k_head<<<B, 128>>>(conv2_w, conv2_b, fc1_w, fc1_b, fc2_w, fc2_b, out);
}

// round 6
// speedup vs baseline: 4.4030x; 1.9304x over previous
#include <cuda_runtime.h>
#include <cuda_bf16.h>

#define B 512
#define S 1024
#define I 20
#define H 64
#define G 256   // 4*H gates
#define NB 8    // batches (chains) per LSTM CTA

// ---- scratch (device globals; no allocation allowed) ----
__device__ int   g_tok[B * S];     // token index per (b,s), -1 if padding
__device__ int   g_len[B];         // true sequence length
__device__ float g_h[2][B * H];    // final hidden states fw/bw
__device__ float g_avblock[B * 80];

__device__ __forceinline__ float tanh_fast(float x) {
    float y;
    asm("tanh.approx.f32 %0, %1;" : "=f"(y) : "f"(x));
    return y;
}
__device__ __forceinline__ float sig_fast(float x) {
    return fmaf(tanh_fast(0.5f * x), 0.5f, 0.5f);
}
__device__ __forceinline__ unsigned cvt_tf32(float x) {
    unsigned u;
    asm("cvt.rna.tf32.f32 %0, %1;" : "=r"(u) : "f"(x));
    return u;
}
__device__ __forceinline__ void mma_tf32(float d[4],
                                         unsigned a0, unsigned a1,
                                         unsigned a2, unsigned a3,
                                         unsigned b0, unsigned b1) {
    asm volatile(
        "mma.sync.aligned.m16n8k8.row.col.f32.tf32.tf32.f32 "
        "{%0,%1,%2,%3}, {%4,%5,%6,%7}, {%8,%9}, {%0,%1,%2,%3};"
        : "+f"(d[0]), "+f"(d[1]), "+f"(d[2]), "+f"(d[3])
        : "r"(a0), "r"(a1), "r"(a2), "r"(a3), "r"(b0), "r"(b1));
}

// ============================================================
// Kernel 1: tokenize one-hot input + compute lengths
// ============================================================
__global__ void k_tokenize(const float* __restrict__ input1) {
    int b = blockIdx.x;
    int tid = threadIdx.x;
    __shared__ int s_cnt[256];
    int cnt = 0;
    for (int s = tid; s < S; s += 256) {
        const float4* row = (const float4*)(input1 + ((size_t)b * S + s) * I);
        int t = -1;
        #pragma unroll
        for (int q = 0; q < 5; q++) {
            float4 v = row[q];
            if (v.x > 0.5f) t = q * 4 + 0;
            if (v.y > 0.5f) t = q * 4 + 1;
            if (v.z > 0.5f) t = q * 4 + 2;
            if (v.w > 0.5f) t = q * 4 + 3;
        }
        g_tok[b * S + s] = t;
        if (t >= 0) cnt++;
    }
    s_cnt[tid] = cnt;
    __syncthreads();
    for (int off = 128; off > 0; off >>= 1) {
        if (tid < off) s_cnt[tid] += s_cnt[tid + off];
        __syncthreads();
    }
    if (tid == 0) g_len[b] = s_cnt[0];
}

// ============================================================
// Kernel 2: tensor-core LSTM. One CTA = 8 chains of one direction.
// 8 warps; warp w owns gate slice [w*32, w*32+32).
// W_hh lives in mma B-fragments (64 regs/warp) for all 1024 steps.
// Per step: gates[16,256] = h[16,64] @ W_hh^T via m16n8k8 tf32 mma
// (rows 8..15 are zero padding), then fused activation.
// ============================================================
#define HSTRIDE 68    // padded row stride of h in SMEM (conflict-free A loads)
#define GSTRIDE 260   // padded row stride of gates in SMEM

__global__ void __launch_bounds__(256, 1)
k_lstm(const float* __restrict__ W_ih_f, const float* __restrict__ W_hh_f,
       const float* __restrict__ b_f,
       const float* __restrict__ W_ih_b, const float* __restrict__ W_hh_b,
       const float* __restrict__ b_b) {
    int b0  = blockIdx.x * NB;
    int dir = blockIdx.y;
    int t    = threadIdx.x;
    int w    = t >> 5;         // warp 0..7
    int lane = t & 31;
    int gID  = lane >> 2;      // 0..7 (row group)
    int tig  = lane & 3;       // 0..3

    const float* W_ih = dir ? W_ih_b : W_ih_f;
    const float* W_hh = dir ? W_hh_b : W_hh_f;
    const float* bias = dir ? b_b    : b_f;

    __shared__ float s_Wihb[21 * G];        // [tok][gate] bias-fused; row 20 = bias only
    __shared__ float s_h[16 * HSTRIDE];     // h (tf32-rounded), rows 8..15 stay zero
    __shared__ float s_gates[8 * GSTRIDE];  // mma output rows 0..7
    __shared__ signed char s_tok[NB * S];

    // stage W_ih transposed with bias fused
    for (int idx = t; idx < 21 * G; idx += 256) {
        int i  = idx >> 8;
        int gg = idx & 255;
        float v = bias[gg];
        if (i < I) v += W_ih[gg * I + i];
        s_Wihb[idx] = v;
    }
    for (int idx = t; idx < NB * S; idx += 256) {
        int nb = idx >> 10, s = idx & (S - 1);
        s_tok[idx] = (signed char)g_tok[(b0 + nb) * S + s];
    }
    for (int idx = t; idx < 16 * HSTRIDE; idx += 256) s_h[idx] = 0.0f;

    // B fragments: W_hh gate rows for this warp's n-slice, tf32
    unsigned bf[8][4][2];
    #pragma unroll
    for (int kt = 0; kt < 8; kt++) {
        #pragma unroll
        for (int j = 0; j < 4; j++) {
            int gate = w * 32 + j * 8 + gID;
            bf[kt][j][0] = cvt_tf32(W_hh[gate * H + kt * 8 + tig]);
            bf[kt][j][1] = cvt_tf32(W_hh[gate * H + kt * 8 + tig + 4]);
        }
    }

    // activation role: thread t -> batch ab (0..7), hid units ah, ah+1
    int ab = t >> 5;
    int ah = (t & 31) * 2;
    float cs0 = 0.0f, cs1 = 0.0f;   // cell states
    float hx = 0.0f, hy = 0.0f;     // full-precision h (for final output)
    __syncthreads();

    for (int step = 0; step < S; step++) {
        int s = dir ? (S - 1 - step) : step;

        // ---- MMA phase ----
        float d[4][4] = {{0.f,0.f,0.f,0.f},{0.f,0.f,0.f,0.f},
                         {0.f,0.f,0.f,0.f},{0.f,0.f,0.f,0.f}};
        #pragma unroll
        for (int kt = 0; kt < 8; kt++) {
            int ko = kt * 8 + tig;
            unsigned a0 = __float_as_uint(s_h[gID * HSTRIDE + ko]);
            unsigned a1 = __float_as_uint(s_h[(gID + 8) * HSTRIDE + ko]);
            unsigned a2 = __float_as_uint(s_h[gID * HSTRIDE + ko + 4]);
            unsigned a3 = __float_as_uint(s_h[(gID + 8) * HSTRIDE + ko + 4]);
            #pragma unroll
            for (int j = 0; j < 4; j++)
                mma_tf32(d[j], a0, a1, a2, a3, bf[kt][j][0], bf[kt][j][1]);
        }
        // store rows 0..7 of D (c0,c1 = row gID, cols 2tig, 2tig+1)
        #pragma unroll
        for (int j = 0; j < 4; j++) {
            *(float2*)(s_gates + gID * GSTRIDE + w * 32 + j * 8 + 2 * tig) =
                make_float2(d[j][0], d[j][1]);
        }
        __syncthreads();

        // ---- activation phase ----
        {
            int tok = s_tok[ab * S + s];
            int row = (tok >= 0) ? tok : 20;
            const float* gp = s_gates + ab * GSTRIDE + ah;
            const float* ip = s_Wihb + row * G + ah;
            float2 mi = *(const float2*)(gp);
            float2 mf = *(const float2*)(gp + H);
            float2 mg = *(const float2*)(gp + 2 * H);
            float2 mo = *(const float2*)(gp + 3 * H);
            float2 ii = *(const float2*)(ip);
            float2 ff = *(const float2*)(ip + H);
            float2 ggv = *(const float2*)(ip + 2 * H);
            float2 oo = *(const float2*)(ip + 3 * H);
            float igx = mi.x + ii.x,  igy = mi.y + ii.y;
            float fgx = mf.x + ff.x,  fgy = mf.y + ff.y;
            float ggx = mg.x + ggv.x, ggy = mg.y + ggv.y;
            float ogx = mo.x + oo.x,  ogy = mo.y + oo.y;
            cs0 = sig_fast(fgx) * cs0 + sig_fast(igx) * tanh_fast(ggx);
            cs1 = sig_fast(fgy) * cs1 + sig_fast(igy) * tanh_fast(ggy);
            hx = sig_fast(ogx) * tanh_fast(cs0);
            hy = sig_fast(ogy) * tanh_fast(cs1);
            s_h[ab * HSTRIDE + ah]     = __uint_as_float(cvt_tf32(hx));
            s_h[ab * HSTRIDE + ah + 1] = __uint_as_float(cvt_tf32(hy));
        }
        __syncthreads();
    }

    // final hidden state (full precision from registers)
    *(float2*)(&g_h[dir][(b0 + ab) * H + ah]) = make_float2(hx, hy);
}

// ============================================================
// Kernel 3: conv1 (token gather) + torch-reshape + ragged 4-bin mean
// ============================================================
__global__ void k_avblock(const float* __restrict__ conv1_w) {
    int b = blockIdx.x;
    int tid = threadIdx.x;
    __shared__ int   s_tok[S];
    __shared__ float s_w[I * I];
    for (int s = tid; s < S; s += 128) s_tok[s] = g_tok[b * S + s];
    for (int i = tid; i < I * I; i += 128) s_w[i] = conv1_w[i];
    __syncthreads();

    int bw = g_len[b] / 4;
    if (tid < 80) {
        int k = tid / I, cc = tid % I;
        float sum = 0.0f;
        for (int s = k * bw; s < (k + 1) * bw; s++) {
            int flat = s * I + cc;
            int ch = flat >> 10;       // flat / S  (S=1024)
            int pp = flat & (S - 1);   // flat % S
            int tk = s_tok[pp];
            if (tk >= 0) sum += s_w[ch * I + tk];
        }
        g_avblock[b * 80 + tid] = sum / (float)bw;
    }
}

// ============================================================
// Kernel 4: conv2+relu, concat, fc1, fc2, softmax
// ============================================================
__global__ void k_head(const float* __restrict__ conv2_w,
                       const float* __restrict__ conv2_b,
                       const float* __restrict__ fc1_w,
                       const float* __restrict__ fc1_b,
                       const float* __restrict__ fc2_w,
                       const float* __restrict__ fc2_b,
                       float* __restrict__ out) {
    int b = blockIdx.x;
    int tid = threadIdx.x;
    __shared__ float s_m[228];
    __shared__ float s_av[80];
    __shared__ float s_f[64];

    if (tid < 64)            s_m[tid] = g_h[0][b * H + tid];
    else if (tid < 128)      s_m[tid] = g_h[1][b * H + tid - 64];
    if (tid < 80)            s_av[tid] = g_avblock[b * 80 + tid];
    __syncthreads();

    if (tid < 100) {
        float acc = conv2_b[tid];
        const float* w = conv2_w + tid * 80;
        #pragma unroll 8
        for (int j = 0; j < 80; j++) acc = fmaf(s_av[j], w[j], acc);
        s_m[128 + tid] = fmaxf(acc, 0.0f);
    }
    __syncthreads();

    if (tid < 64) {
        float acc = fc1_b[tid];
        const float* w = fc1_w + tid * 228;
        for (int j = 0; j < 228; j++) acc = fmaf(s_m[j], w[j], acc);
        s_f[tid] = acc;
    }
    __syncthreads();

    if (tid == 0) {
        float a0 = fc2_b[0], a1 = fc2_b[1];
        #pragma unroll 8
        for (int j = 0; j < 64; j++) {
            a0 = fmaf(s_f[j], fc2_w[j], a0);
            a1 = fmaf(s_f[j], fc2_w[64 + j], a1);
        }
        float m  = fmaxf(a0, a1);
        float e0 = __expf(a0 - m), e1 = __expf(a1 - m);
        float inv = 1.0f / (e0 + e1);
        out[b * 2 + 0] = e0 * inv;
        out[b * 2 + 1] = e1 * inv;
    }
}

extern "C" void kernel_launch(void* const* d_in, const int* in_sizes, int n_in,
                              void* d_out, int out_size) {
    const float* input1  = (const float*)d_in[0];
    const float* W_ih_f  = (const float*)d_in[1];
    const float* W_hh_f  = (const float*)d_in[2];
    const float* b_f     = (const float*)d_in[3];
    const float* W_ih_b  = (const float*)d_in[4];
    const float* W_hh_b  = (const float*)d_in[5];
    const float* b_b     = (const float*)d_in[6];
    const float* conv1_w = (const float*)d_in[7];
    const float* conv2_w = (const float*)d_in[8];
    const float* conv2_b = (const float*)d_in[9];
    const float* fc1_w   = (const float*)d_in[10];
    const float* fc1_b   = (const float*)d_in[11];
    const float* fc2_w   = (const float*)d_in[12];
    const float* fc2_b   = (const float*)d_in[13];
    float* out = (float*)d_out;

    k_tokenize<<<B, 256>>>(input1);
    dim3 lgrid(B / NB, 2);
    k_lstm<<<lgrid, 256>>>(W_ih_f, W_hh_f, b_f, W_ih_b, W_hh_b, b_b);
    k_avblock<<<B, 128>>>(conv1_w);
    k_head<<<B, 128>>>(conv2_w, conv2_b, fc1_w, fc1_b, fc2_w, fc2_b, out);
}

// round 7
// speedup vs baseline: 6.0094x; 1.3648x over previous
#include <cuda_runtime.h>
#include <cuda_fp16.h>
#include <cuda_bf16.h>

#define B 512
#define S 1024
#define I 20
#define H 64
#define G 256    // 4*H gates
#define NB 7     // batches (chains) per LSTM CTA -> 74*2 = 148 CTAs = 1/SM
#define NCTA 74  // ceil(512/7)
#define HSH 72   // half-element stride of h rows in SMEM (bank-shift 4/row)
#define GSTRIDE 260

// ---- scratch (device globals; no allocation allowed) ----
__device__ int   g_tok[B * S];     // token index per (b,s), -1 if padding
__device__ int   g_len[B];         // true sequence length
__device__ float g_h[2][B * H];    // final hidden states fw/bw
__device__ float g_avblock[B * 80];

__device__ __forceinline__ float tanh_fast(float x) {
    float y;
    asm("tanh.approx.f32 %0, %1;" : "=f"(y) : "f"(x));
    return y;
}
__device__ __forceinline__ float sig_fast(float x) {
    return fmaf(tanh_fast(0.5f * x), 0.5f, 0.5f);
}
__device__ __forceinline__ unsigned pack_h2(float lo, float hi) {
    __half2 h = __floats2half2_rn(lo, hi);
    return *reinterpret_cast<unsigned*>(&h);
}
__device__ __forceinline__ void mma_f16(float d[4],
                                        unsigned a0, unsigned a1,
                                        unsigned a2, unsigned a3,
                                        unsigned b0, unsigned b1) {
    asm volatile(
        "mma.sync.aligned.m16n8k16.row.col.f32.f16.f16.f32 "
        "{%0,%1,%2,%3}, {%4,%5,%6,%7}, {%8,%9}, {%0,%1,%2,%3};"
        : "+f"(d[0]), "+f"(d[1]), "+f"(d[2]), "+f"(d[3])
        : "r"(a0), "r"(a1), "r"(a2), "r"(a3), "r"(b0), "r"(b1));
}

// ============================================================
// Kernel 1: tokenize one-hot input + compute lengths
// ============================================================
__global__ void k_tokenize(const float* __restrict__ input1) {
    int b = blockIdx.x;
    int tid = threadIdx.x;
    __shared__ int s_cnt[256];
    int cnt = 0;
    for (int s = tid; s < S; s += 256) {
        const float4* row = (const float4*)(input1 + ((size_t)b * S + s) * I);
        int t = -1;
        #pragma unroll
        for (int q = 0; q < 5; q++) {
            float4 v = row[q];
            if (v.x > 0.5f) t = q * 4 + 0;
            if (v.y > 0.5f) t = q * 4 + 1;
            if (v.z > 0.5f) t = q * 4 + 2;
            if (v.w > 0.5f) t = q * 4 + 3;
        }
        g_tok[b * S + s] = t;
        if (t >= 0) cnt++;
    }
    s_cnt[tid] = cnt;
    __syncthreads();
    for (int off = 128; off > 0; off >>= 1) {
        if (tid < off) s_cnt[tid] += s_cnt[tid + off];
        __syncthreads();
    }
    if (tid == 0) g_len[b] = s_cnt[0];
}

// ============================================================
// Kernel 2: fp16 tensor-core LSTM. One CTA = 7 chains of one direction.
// 8 warps; warp w owns gate slice [w*32, w*32+32).
// W_hh lives in fp16 mma B-fragments (32 regs/warp) for all 1024 steps.
// Per step: gates[16,256] = h[16,64] @ W_hh^T via m16n8k16 fp16 mma.
// A rows 8..15 are structurally zero -> a1 = a3 = 0 (no loads).
// ============================================================
__global__ void __launch_bounds__(256, 1)
k_lstm(const float* __restrict__ W_ih_f, const float* __restrict__ W_hh_f,
       const float* __restrict__ b_f,
       const float* __restrict__ W_ih_b, const float* __restrict__ W_hh_b,
       const float* __restrict__ b_b) {
    int b0  = blockIdx.x * NB;
    int dir = blockIdx.y;
    int t    = threadIdx.x;
    int w    = t >> 5;         // warp 0..7
    int lane = t & 31;
    int gID  = lane >> 2;      // 0..7
    int tig  = lane & 3;       // 0..3

    const float* W_ih = dir ? W_ih_b : W_ih_f;
    const float* W_hh = dir ? W_hh_b : W_hh_f;
    const float* bias = dir ? b_b    : b_f;

    __shared__ float  s_Wihb[21 * G];        // [tok][gate] bias-fused; row 20 = bias only
    __shared__ __half s_h[8 * HSH];          // h rows 0..7 (fp16); rows 8..15 implicit 0
    __shared__ float  s_gates[8 * GSTRIDE];  // mma D rows 0..7
    __shared__ signed char s_tok[NB * S];

    // stage W_ih transposed with bias fused
    for (int idx = t; idx < 21 * G; idx += 256) {
        int i  = idx >> 8;
        int gg = idx & 255;
        float v = bias[gg];
        if (i < I) v += W_ih[gg * I + i];
        s_Wihb[idx] = v;
    }
    // stage tokens (guard batches past B -> bias-only row)
    for (int idx = t; idx < NB * S; idx += 256) {
        int nb = idx / S, s = idx & (S - 1);
        int bb = b0 + nb;
        s_tok[idx] = (bb < B) ? (signed char)g_tok[bb * S + s] : (signed char)-1;
    }
    // zero h
    for (int idx = t; idx < 8 * HSH / 2; idx += 256)
        ((unsigned*)s_h)[idx] = 0u;

    // B fragments: W_hh for this warp's 32 gates, fp16
    unsigned bf[4][4][2];
    #pragma unroll
    for (int kt = 0; kt < 4; kt++) {
        #pragma unroll
        for (int j = 0; j < 4; j++) {
            int gate = w * 32 + j * 8 + gID;
            int k0 = kt * 16 + 2 * tig;
            const float* wr = W_hh + gate * H;
            bf[kt][j][0] = pack_h2(wr[k0],     wr[k0 + 1]);
            bf[kt][j][1] = pack_h2(wr[k0 + 8], wr[k0 + 9]);
        }
    }

    // activation role: thread t -> batch ab (0..6 valid), hid units ah, ah+1
    int ab = t >> 5;
    int ah = (t & 31) * 2;
    bool act = (t < NB * 32);
    float cs0 = 0.0f, cs1 = 0.0f;
    float hx = 0.0f, hy = 0.0f;
    __syncthreads();

    for (int step = 0; step < S; step++) {
        int s = dir ? (S - 1 - step) : step;

        // ---- MMA phase (fp16, K=64 in 4 chunks) ----
        float d[4][4] = {{0.f,0.f,0.f,0.f},{0.f,0.f,0.f,0.f},
                         {0.f,0.f,0.f,0.f},{0.f,0.f,0.f,0.f}};
        #pragma unroll
        for (int kt = 0; kt < 4; kt++) {
            int k0 = kt * 16 + 2 * tig;
            unsigned a0 = *(const unsigned*)(s_h + gID * HSH + k0);
            unsigned a2 = *(const unsigned*)(s_h + gID * HSH + k0 + 8);
            #pragma unroll
            for (int j = 0; j < 4; j++)
                mma_f16(d[j], a0, 0u, a2, 0u, bf[kt][j][0], bf[kt][j][1]);
        }
        #pragma unroll
        for (int j = 0; j < 4; j++) {
            *(float2*)(s_gates + gID * GSTRIDE + w * 32 + j * 8 + 2 * tig) =
                make_float2(d[j][0], d[j][1]);
        }
        __syncthreads();

        // ---- activation phase ----
        if (act) {
            int tok = s_tok[ab * S + s];
            int row = (tok >= 0) ? tok : 20;
            const float* gp = s_gates + ab * GSTRIDE + ah;
            const float* ip = s_Wihb + row * G + ah;
            float2 mi = *(const float2*)(gp);
            float2 mf = *(const float2*)(gp + H);
            float2 mg = *(const float2*)(gp + 2 * H);
            float2 mo = *(const float2*)(gp + 3 * H);
            float2 ii = *(const float2*)(ip);
            float2 ff = *(const float2*)(ip + H);
            float2 gv = *(const float2*)(ip + 2 * H);
            float2 oo = *(const float2*)(ip + 3 * H);
            float igx = mi.x + ii.x,  igy = mi.y + ii.y;
            float fgx = mf.x + ff.x,  fgy = mf.y + ff.y;
            float ggx = mg.x + gv.x,  ggy = mg.y + gv.y;
            float ogx = mo.x + oo.x,  ogy = mo.y + oo.y;
            cs0 = sig_fast(fgx) * cs0 + sig_fast(igx) * tanh_fast(ggx);
            cs1 = sig_fast(fgy) * cs1 + sig_fast(igy) * tanh_fast(ggy);
            hx = sig_fast(ogx) * tanh_fast(cs0);
            hy = sig_fast(ogy) * tanh_fast(cs1);
            *(__half2*)(s_h + ab * HSH + ah) = __floats2half2_rn(hx, hy);
        }
        __syncthreads();
    }

    if (act && (b0 + ab) < B)
        *(float2*)(&g_h[dir][(b0 + ab) * H + ah]) = make_float2(hx, hy);
}

// ============================================================
// Kernel 3: conv1 (token gather) + torch-reshape + ragged 4-bin mean
// ============================================================
__global__ void k_avblock(const float* __restrict__ conv1_w) {
    int b = blockIdx.x;
    int tid = threadIdx.x;
    __shared__ int   s_tok[S];
    __shared__ float s_w[I * I];
    for (int s = tid; s < S; s += 128) s_tok[s] = g_tok[b * S + s];
    for (int i = tid; i < I * I; i += 128) s_w[i] = conv1_w[i];
    __syncthreads();

    int bw = g_len[b] / 4;
    if (tid < 80) {
        int k = tid / I, cc = tid % I;
        float sum = 0.0f;
        for (int s = k * bw; s < (k + 1) * bw; s++) {
            int flat = s * I + cc;
            int ch = flat >> 10;       // flat / S  (S=1024)
            int pp = flat & (S - 1);   // flat % S
            int tk = s_tok[pp];
            if (tk >= 0) sum += s_w[ch * I + tk];
        }
        g_avblock[b * 80 + tid] = sum / (float)bw;
    }
}

// ============================================================
// Kernel 4: conv2+relu, concat, fc1, fc2, softmax
// ============================================================
__global__ void k_head(const float* __restrict__ conv2_w,
                       const float* __restrict__ conv2_b,
                       const float* __restrict__ fc1_w,
                       const float* __restrict__ fc1_b,
                       const float* __restrict__ fc2_w,
                       const float* __restrict__ fc2_b,
                       float* __restrict__ out) {
    int b = blockIdx.x;
    int tid = threadIdx.x;
    __shared__ float s_m[232];
    __shared__ float s_av[80];
    __shared__ float s_f[64];

    if (tid < 64)            s_m[tid] = g_h[0][b * H + tid];
    else if (tid < 128)      s_m[tid] = g_h[1][b * H + tid - 64];
    if (tid < 80)            s_av[tid] = g_avblock[b * 80 + tid];
    if (tid >= 100 && tid < 104) s_m[128 + tid] = 0.0f;  // pad 228..231
    __syncthreads();

    if (tid < 100) {
        float acc = conv2_b[tid];
        const float* w = conv2_w + tid * 80;
        float a0 = 0.f, a1 = 0.f, a2 = 0.f, a3 = 0.f;
        #pragma unroll
        for (int j = 0; j < 80; j += 4) {
            a0 = fmaf(s_av[j],     w[j],     a0);
            a1 = fmaf(s_av[j + 1], w[j + 1], a1);
            a2 = fmaf(s_av[j + 2], w[j + 2], a2);
            a3 = fmaf(s_av[j + 3], w[j + 3], a3);
        }
        s_m[128 + tid] = fmaxf(acc + (a0 + a1) + (a2 + a3), 0.0f);
    }
    __syncthreads();

    if (tid < 64) {
        const float* w = fc1_w + tid * 228;
        float a0 = 0.f, a1 = 0.f, a2 = 0.f, a3 = 0.f;
        for (int j = 0; j < 228; j += 4) {
            a0 = fmaf(s_m[j],     w[j],     a0);
            a1 = fmaf(s_m[j + 1], w[j + 1], a1);
            a2 = fmaf(s_m[j + 2], w[j + 2], a2);
            a3 = fmaf(s_m[j + 3], w[j + 3], a3);
        }
        s_f[tid] = fc1_b[tid] + (a0 + a1) + (a2 + a3);
    }
    __syncthreads();

    if (tid < 32) {
        float v0 = s_f[tid], v1 = s_f[tid + 32];
        float p0 = v0 * fc2_w[tid]      + v1 * fc2_w[tid + 32];
        float p1 = v0 * fc2_w[64 + tid] + v1 * fc2_w[96 + tid];
        #pragma unroll
        for (int o = 16; o > 0; o >>= 1) {
            p0 += __shfl_xor_sync(0xffffffffu, p0, o);
            p1 += __shfl_xor_sync(0xffffffffu, p1, o);
        }
        if (tid == 0) {
            float a0 = p0 + fc2_b[0], a1 = p1 + fc2_b[1];
            float m  = fmaxf(a0, a1);
            float e0 = __expf(a0 - m), e1 = __expf(a1 - m);
            float inv = 1.0f / (e0 + e1);
            out[b * 2 + 0] = e0 * inv;
            out[b * 2 + 1] = e1 * inv;
        }
    }
}

extern "C" void kernel_launch(void* const* d_in, const int* in_sizes, int n_in,
                              void* d_out, int out_size) {
    const float* input1  = (const float*)d_in[0];
    const float* W_ih_f  = (const float*)d_in[1];
    const float* W_hh_f  = (const float*)d_in[2];
    const float* b_f     = (const float*)d_in[3];
    const float* W_ih_b  = (const float*)d_in[4];
    const float* W_hh_b  = (const float*)d_in[5];
    const float* b_b     = (const float*)d_in[6];
    const float* conv1_w = (const float*)d_in[7];
    const float* conv2_w = (const float*)d_in[8];
    const float* conv2_b = (const float*)d_in[9];
    const float* fc1_w   = (const float*)d_in[10];
    const float* fc1_b   = (const float*)d_in[11];
    const float* fc2_w   = (const float*)d_in[12];
    const float* fc2_b   = (const float*)d_in[13];
    float* out = (float*)d_out;

    k_tokenize<<<B, 256>>>(input1);
    dim3 lgrid(NCTA, 2);
    k_lstm<<<lgrid, 256>>>(W_ih_f, W_hh_f, b_f, W_ih_b, W_hh_b, b_b);
    k_avblock<<<B, 128>>>(conv1_w);
    k_head<<<B, 128>>>(conv2_w, conv2_b, fc1_w, fc1_b, fc2_w, fc2_b, out);
}

// round 9
// speedup vs baseline: 6.9592x; 1.1581x over previous
#include <cuda_runtime.h>
#include <cuda_fp16.h>
#include <cuda_bf16.h>

#define B 512
#define S 1024
#define I 20
#define H 64
#define G 256    // 4*H gates
#define NB 7     // batches (chains) per LSTM CTA -> 74*2 = 148 CTAs = 1/SM
#define NCTA 74
#define HSH 72   // half-element stride of h rows in SMEM
#define GS 260   // float stride of s_gates rows [batch][gate]

// ---- scratch (device globals; no allocation allowed) ----
__device__ int   g_tok[B * S];
__device__ int   g_len[B];
__device__ float g_h[2][B * H];
__device__ float g_avblock[B * 80];

__device__ __forceinline__ unsigned pack_h2(float lo, float hi) {
    __half2 h = __floats2half2_rn(lo, hi);
    return *reinterpret_cast<unsigned*>(&h);
}
__device__ __forceinline__ __half2 h2tanh_fast(__half2 x) {
    unsigned xi = *reinterpret_cast<unsigned*>(&x);
    unsigned yi;
    asm("tanh.approx.f16x2 %0, %1;" : "=r"(yi) : "r"(xi));
    return *reinterpret_cast<__half2*>(&yi);
}
__device__ __forceinline__ __half2 sig2_fast(__half2 x, __half2 h05) {
    return __hfma2(h2tanh_fast(__hmul2(x, h05)), h05, h05);
}
__device__ __forceinline__ void mma_f16(float d[4],
                                        unsigned a0, unsigned a1,
                                        unsigned a2, unsigned a3,
                                        unsigned b0, unsigned b1) {
    asm volatile(
        "mma.sync.aligned.m16n8k16.row.col.f32.f16.f16.f32 "
        "{%0,%1,%2,%3}, {%4,%5,%6,%7}, {%8,%9}, {%0,%1,%2,%3};"
        : "+f"(d[0]), "+f"(d[1]), "+f"(d[2]), "+f"(d[3])
        : "r"(a0), "r"(a1), "r"(a2), "r"(a3), "r"(b0), "r"(b1));
}

// ============================================================
// Kernel 1: tokenize one-hot input + compute lengths
// ============================================================
__global__ void k_tokenize(const float* __restrict__ input1) {
    int b = blockIdx.x;
    int tid = threadIdx.x;
    __shared__ int s_cnt[256];
    int cnt = 0;
    for (int s = tid; s < S; s += 256) {
        const float4* row = (const float4*)(input1 + ((size_t)b * S + s) * I);
        int t = -1;
        #pragma unroll
        for (int q = 0; q < 5; q++) {
            float4 v = row[q];
            if (v.x > 0.5f) t = q * 4 + 0;
            if (v.y > 0.5f) t = q * 4 + 1;
            if (v.z > 0.5f) t = q * 4 + 2;
            if (v.w > 0.5f) t = q * 4 + 3;
        }
        g_tok[b * S + s] = t;
        if (t >= 0) cnt++;
    }
    s_cnt[tid] = cnt;
    __syncthreads();
    for (int off = 128; off > 0; off >>= 1) {
        if (tid < off) s_cnt[tid] += s_cnt[tid + off];
        __syncthreads();
    }
    if (tid == 0) g_len[b] = s_cnt[0];
}

// ============================================================
// Kernel 2: fp16 tensor-core LSTM, transposed GEMM:
//   D[256 gates, 8 batches] = W_hh[256,64] @ h^T[64,8]
// 8 warps; warp w owns gate rows [32w, 32w+32) = 2 m16 tiles.
// W_hh lives in A-fragments (32 regs/warp) for all 1024 steps.
// Batch column 7 is padding (s_h row 7 stays zero).
// ============================================================
__global__ void __launch_bounds__(256, 1)
k_lstm(const float* __restrict__ W_ih_f, const float* __restrict__ W_hh_f,
       const float* __restrict__ b_f,
       const float* __restrict__ W_ih_b, const float* __restrict__ W_hh_b,
       const float* __restrict__ b_b) {
    int b0  = blockIdx.x * NB;
    int dir = blockIdx.y;
    int t    = threadIdx.x;
    int w    = t >> 5;
    int lane = t & 31;
    int gID  = lane >> 2;      // 0..7
    int tig  = lane & 3;       // 0..3

    const float* W_ih = dir ? W_ih_b : W_ih_f;
    const float* W_hh = dir ? W_hh_b : W_hh_f;
    const float* bias = dir ? b_b    : b_f;

    __shared__ float  s_Wihb[21 * G];   // [tok][gate] bias-fused; row 20 = bias only
    __shared__ __half s_h[8 * HSH];     // h rows = batches 0..7 (row 7 stays 0)
    __shared__ float  s_gates[8 * GS];  // [batch][gate]
    __shared__ signed char s_tok[NB * S];

    for (int idx = t; idx < 21 * G; idx += 256) {
        int i  = idx >> 8;
        int gg = idx & 255;
        float v = bias[gg];
        if (i < I) v += W_ih[gg * I + i];
        s_Wihb[idx] = v;
    }
    for (int idx = t; idx < NB * S; idx += 256) {
        int nb = idx / S, s = idx & (S - 1);
        int bb = b0 + nb;
        s_tok[idx] = (bb < B) ? (signed char)g_tok[bb * S + s] : (signed char)-1;
    }
    for (int idx = t; idx < 8 * HSH / 2; idx += 256)
        ((unsigned*)s_h)[idx] = 0u;

    // A fragments: W_hh rows for this warp's 32 gates (2 m16 tiles x 4 K-chunks)
    unsigned af[4][2][4];
    #pragma unroll
    for (int kt = 0; kt < 4; kt++) {
        #pragma unroll
        for (int j = 0; j < 2; j++) {
            int gb = w * 32 + j * 16;
            int k0 = kt * 16 + 2 * tig;
            const float* r0 = W_hh + (gb + gID) * H;
            const float* r1 = W_hh + (gb + gID + 8) * H;
            af[kt][j][0] = pack_h2(r0[k0],     r0[k0 + 1]);
            af[kt][j][1] = pack_h2(r1[k0],     r1[k0 + 1]);
            af[kt][j][2] = pack_h2(r0[k0 + 8], r0[k0 + 9]);
            af[kt][j][3] = pack_h2(r1[k0 + 8], r1[k0 + 9]);
        }
    }

    // activation role: warp ab handles batch ab (0..6), units 2*lane, 2*lane+1
    int ab = t >> 5;
    int ah = (t & 31) * 2;
    bool act = (ab < NB);
    float cs0 = 0.0f, cs1 = 0.0f;
    float hx = 0.0f, hy = 0.0f;
    const __half2 h05 = __float2half2_rn(0.5f);
    __syncthreads();

    for (int step = 0; step < S; step++) {
        int s = dir ? (S - 1 - step) : step;

        // ---- MMA phase: 8 mma/warp, B-frags shared across the 2 M tiles ----
        float d0[4] = {0.f, 0.f, 0.f, 0.f};
        float d1[4] = {0.f, 0.f, 0.f, 0.f};
        #pragma unroll
        for (int kt = 0; kt < 4; kt++) {
            int k0 = kt * 16 + 2 * tig;
            unsigned bb0 = *(const unsigned*)(s_h + gID * HSH + k0);
            unsigned bb1 = *(const unsigned*)(s_h + gID * HSH + k0 + 8);
            mma_f16(d0, af[kt][0][0], af[kt][0][1], af[kt][0][2], af[kt][0][3], bb0, bb1);
            mma_f16(d1, af[kt][1][0], af[kt][1][1], af[kt][1][2], af[kt][1][3], bb0, bb1);
        }
        // scatter D into [batch][gate] (conflict-free scalar stores)
        {
            int m0 = w * 32 + gID;
            int r0 = (2 * tig) * GS, r1 = (2 * tig + 1) * GS;
            s_gates[r0 + m0]      = d0[0];
            s_gates[r1 + m0]      = d0[1];
            s_gates[r0 + m0 + 8]  = d0[2];
            s_gates[r1 + m0 + 8]  = d0[3];
            s_gates[r0 + m0 + 16] = d1[0];
            s_gates[r1 + m0 + 16] = d1[1];
            s_gates[r0 + m0 + 24] = d1[2];
            s_gates[r1 + m0 + 24] = d1[3];
        }
        __syncthreads();

        // ---- activation phase (f16x2 nonlinearities, fp32 cell state) ----
        if (act) {
            int tok = s_tok[ab * S + s];
            int row = (tok >= 0) ? tok : 20;
            const float* gp = s_gates + ab * GS + ah;
            const float* ip = s_Wihb + row * G + ah;
            float2 mi = *(const float2*)(gp);
            float2 mf = *(const float2*)(gp + H);
            float2 mg = *(const float2*)(gp + 2 * H);
            float2 mo = *(const float2*)(gp + 3 * H);
            float2 ii = *(const float2*)(ip);
            float2 ff = *(const float2*)(ip + H);
            float2 gv = *(const float2*)(ip + 2 * H);
            float2 oo = *(const float2*)(ip + 3 * H);
            __half2 I2 = __floats2half2_rn(mi.x + ii.x, mi.y + ii.y);
            __half2 F2 = __floats2half2_rn(mf.x + ff.x, mf.y + ff.y);
            __half2 G2 = __floats2half2_rn(mg.x + gv.x, mg.y + gv.y);
            __half2 O2 = __floats2half2_rn(mo.x + oo.x, mo.y + oo.y);
            __half2 sI = sig2_fast(I2, h05);
            __half2 sF = sig2_fast(F2, h05);
            __half2 sO = sig2_fast(O2, h05);
            __half2 tG = h2tanh_fast(G2);
            float2 fF = __half22float2(sF);
            float2 pp = __half22float2(__hmul2(sI, tG));
            cs0 = fF.x * cs0 + pp.x;
            cs1 = fF.y * cs1 + pp.y;
            __half2 tC = h2tanh_fast(__floats2half2_rn(cs0, cs1));
            __half2 hv = __hmul2(sO, tC);
            *(__half2*)(s_h + ab * HSH + ah) = hv;
            float2 fh = __half22float2(hv);
            hx = fh.x; hy = fh.y;
        }
        __syncthreads();
    }

    if (act && (b0 + ab) < B)
        *(float2*)(&g_h[dir][(b0 + ab) * H + ah]) = make_float2(hx, hy);
}

// ============================================================
// Kernel 3: conv1 (token gather) + torch-reshape + ragged 4-bin mean
// ============================================================
__global__ void k_avblock(const float* __restrict__ conv1_w) {
    int b = blockIdx.x;
    int tid = threadIdx.x;
    __shared__ int   s_tok[S];
    __shared__ float s_w[I * I];
    for (int s = tid; s < S; s += 128) s_tok[s] = g_tok[b * S + s];
    for (int i = tid; i < I * I; i += 128) s_w[i] = conv1_w[i];
    __syncthreads();

    int bw = g_len[b] / 4;
    if (tid < 80) {
        int k = tid / I, cc = tid % I;
        float sum = 0.0f;
        for (int s = k * bw; s < (k + 1) * bw; s++) {
            int flat = s * I + cc;
            int ch = flat >> 10;
            int pp = flat & (S - 1);
            int tk = s_tok[pp];
            if (tk >= 0) sum += s_w[ch * I + tk];
        }
        g_avblock[b * 80 + tid] = sum / (float)bw;
    }
}

// ============================================================
// Kernel 4: conv2+relu, concat, fc1, fc2, softmax
// ============================================================
__global__ void k_head(const float* __restrict__ conv2_w,
                       const float* __restrict__ conv2_b,
                       const float* __restrict__ fc1_w,
                       const float* __restrict__ fc1_b,
                       const float* __restrict__ fc2_w,
                       const float* __restrict__ fc2_b,
                       float* __restrict__ out) {
    int b = blockIdx.x;
    int tid = threadIdx.x;
    __shared__ float s_m[232];
    __shared__ float s_av[80];
    __shared__ float s_f[64];

    if (tid < 64)            s_m[tid] = g_h[0][b * H + tid];
    else if (tid < 128)      s_m[tid] = g_h[1][b * H + tid - 64];
    if (tid < 80)            s_av[tid] = g_avblock[b * 80 + tid];
    if (tid >= 100 && tid < 104) s_m[128 + tid] = 0.0f;
    __syncthreads();

    if (tid < 100) {
        float acc = conv2_b[tid];
        const float* w = conv2_w + tid * 80;
        float a0 = 0.f, a1 = 0.f, a2 = 0.f, a3 = 0.f;
        #pragma unroll
        for (int j = 0; j < 80; j += 4) {
            a0 = fmaf(s_av[j],     w[j],     a0);
            a1 = fmaf(s_av[j + 1], w[j + 1], a1);
            a2 = fmaf(s_av[j + 2], w[j + 2], a2);
            a3 = fmaf(s_av[j + 3], w[j + 3], a3);
        }
        s_m[128 + tid] = fmaxf(acc + (a0 + a1) + (a2 + a3), 0.0f);
    }
    __syncthreads();

    if (tid < 64) {
        const float* w = fc1_w + tid * 228;
        float a0 = 0.f, a1 = 0.f, a2 = 0.f, a3 = 0.f;
        for (int j = 0; j < 228; j += 4) {
            a0 = fmaf(s_m[j],     w[j],     a0);
            a1 = fmaf(s_m[j + 1], w[j + 1], a1);
            a2 = fmaf(s_m[j + 2], w[j + 2], a2);
            a3 = fmaf(s_m[j + 3], w[j + 3], a3);
        }
        s_f[tid] = fc1_b[tid] + (a0 + a1) + (a2 + a3);
    }
    __syncthreads();

    if (tid < 32) {
        float v0 = s_f[tid], v1 = s_f[tid + 32];
        float p0 = v0 * fc2_w[tid]      + v1 * fc2_w[tid + 32];
        float p1 = v0 * fc2_w[64 + tid] + v1 * fc2_w[96 + tid];
        #pragma unroll
        for (int o = 16; o > 0; o >>= 1) {
            p0 += __shfl_xor_sync(0xffffffffu, p0, o);
            p1 += __shfl_xor_sync(0xffffffffu, p1, o);
        }
        if (tid == 0) {
            float a0 = p0 + fc2_b[0], a1 = p1 + fc2_b[1];
            float m  = fmaxf(a0, a1);
            float e0 = __expf(a0 - m), e1 = __expf(a1 - m);
            float inv = 1.0f / (e0 + e1);
            out[b * 2 + 0] = e0 * inv;
            out[b * 2 + 1] = e1 * inv;
        }
    }
}

extern "C" void kernel_launch(void* const* d_in, const int* in_sizes, int n_in,
                              void* d_out, int out_size) {
    const float* input1  = (const float*)d_in[0];
    const float* W_ih_f  = (const float*)d_in[1];
    const float* W_hh_f  = (const float*)d_in[2];
    const float* b_f     = (const float*)d_in[3];
    const float* W_ih_b  = (const float*)d_in[4];
    const float* W_hh_b  = (const float*)d_in[5];
    const float* b_b     = (const float*)d_in[6];
    const float* conv1_w = (const float*)d_in[7];
    const float* conv2_w = (const float*)d_in[8];
    const float* conv2_b = (const float*)d_in[9];
    const float* fc1_w   = (const float*)d_in[10];
    const float* fc1_b   = (const float*)d_in[11];
    const float* fc2_w   = (const float*)d_in[12];
    const float* fc2_b   = (const float*)d_in[13];
    float* out = (float*)d_out;

    k_tokenize<<<B, 256>>>(input1);
    dim3 lgrid(NCTA, 2);
    k_lstm<<<lgrid, 256>>>(W_ih_f, W_hh_f, b_f, W_ih_b, W_hh_b, b_b);
    k_avblock<<<B, 128>>>(conv1_w);
    k_head<<<B, 128>>>(conv2_w, conv2_b, fc1_w, fc1_b, fc2_w, fc2_b, out);
}